// round 4
// baseline (speedup 1.0000x reference)
#include <cuda_runtime.h>
#include <cuda_bf16.h>
#include <cstdint>

#define HID   1024
#define NST   16
#define BATCHN 4
#define SEQ   2048
#define XPC   (2*NST + HID)          // 1056
#define M_ROWS (BATCHN*SEQ)          // 8192
#define NCHUNK 16
#define LC    (SEQ/NCHUNK)           // 128

// ---------------- scratch (no allocations allowed) ----------------
__device__ float g_xp[M_ROWS * XPC];                 // x @ Wx^T
__device__ float g_y [M_ROWS * HID];                 // scan output
__device__ float g_E [NCHUNK*BATCHN*NST*HID];        // per-chunk local end state
__device__ float g_S [NCHUNK*BATCHN*HID];            // per-chunk sum of delta
__device__ float g_h0[NCHUNK*BATCHN*NST*HID];        // per-chunk initial state

// ---------------- helpers ----------------
__device__ __forceinline__ float ex2_(float x) {
    float y;
    asm("ex2.approx.ftz.f32 %0, %1;" : "=f"(y) : "f"(x));
    return y;
}

__device__ __forceinline__ void ldsm4(uint32_t addr, uint32_t& r0, uint32_t& r1,
                                      uint32_t& r2, uint32_t& r3) {
    asm volatile("ldmatrix.sync.aligned.m8n8.x4.shared.b16 {%0,%1,%2,%3}, [%4];"
                 : "=r"(r0), "=r"(r1), "=r"(r2), "=r"(r3) : "r"(addr));
}

__device__ __forceinline__ void mma_bf16(float* c, const uint32_t* a,
                                         uint32_t b0, uint32_t b1) {
    asm volatile(
        "mma.sync.aligned.m16n8k16.row.col.f32.bf16.bf16.f32 "
        "{%0,%1,%2,%3}, {%4,%5,%6,%7}, {%8,%9}, {%0,%1,%2,%3};"
        : "+f"(c[0]), "+f"(c[1]), "+f"(c[2]), "+f"(c[3])
        : "r"(a[0]), "r"(a[1]), "r"(a[2]), "r"(a[3]), "r"(b0), "r"(b1));
}

// ---------------- GEMM: C[M,N] = A[M,K] * B[N,K]^T, fp32 via split-bf16 ----------------
#define BM 128
#define BN 64
#define BK 32
#define LDSA 40   // padded stride (bf16 elems) -> conflict-free ldmatrix
#define LDSB 40

__global__ __launch_bounds__(256)
void gemm_nt(const float* __restrict__ A, const float* __restrict__ B,
             float* __restrict__ C, int M, int N, int K) {
    __shared__ __nv_bfloat16 Ah[BM][LDSA], Al[BM][LDSA];
    __shared__ __nv_bfloat16 Bh[BN][LDSB], Bl[BN][LDSB];

    const int tid  = threadIdx.x;
    const int lane = tid & 31;
    const int warp = tid >> 5;
    const int wm   = (warp >> 1) * 32;   // 0,32,64,96
    const int wn   = (warp & 1) * 32;    // 0,32
    const int bm   = blockIdx.y * BM;
    const int bn   = blockIdx.x * BN;

    const int acol  = (tid & 7) << 2;    // 0..28
    const int arow0 = tid >> 3;          // 0..31

    float acc[2][4][4];
#pragma unroll
    for (int i = 0; i < 2; i++)
#pragma unroll
        for (int j = 0; j < 4; j++)
#pragma unroll
            for (int k = 0; k < 4; k++) acc[i][j][k] = 0.f;

    const uint32_t aBaseH = (uint32_t)__cvta_generic_to_shared(&Ah[0][0]);
    const uint32_t aBaseL = (uint32_t)__cvta_generic_to_shared(&Al[0][0]);
    const uint32_t bBaseH = (uint32_t)__cvta_generic_to_shared(&Bh[0][0]);
    const uint32_t bBaseL = (uint32_t)__cvta_generic_to_shared(&Bl[0][0]);

    float4 aR[4], bR[2];
    const float4 zero4 = make_float4(0.f, 0.f, 0.f, 0.f);

    // prologue load (k-tile 0)
#pragma unroll
    for (int i = 0; i < 4; i++)
        aR[i] = *(const float4*)&A[(size_t)(bm + arow0 + 32*i) * K + acol];
#pragma unroll
    for (int i = 0; i < 2; i++) {
        int gn = bn + arow0 + 32*i;
        bR[i] = (gn < N) ? *(const float4*)&B[(size_t)gn * K + acol] : zero4;
    }

    const int nk = K / BK;
    for (int kt = 0; kt < nk; ++kt) {
        // split & store staged regs to smem
#pragma unroll
        for (int i = 0; i < 4; i++) {
            float v[4] = {aR[i].x, aR[i].y, aR[i].z, aR[i].w};
            union { __nv_bfloat16 b[4]; uint2 u; } ph, pl;
#pragma unroll
            for (int j = 0; j < 4; j++) {
                __nv_bfloat16 hi = __float2bfloat16(v[j]);
                ph.b[j] = hi;
                pl.b[j] = __float2bfloat16(v[j] - __bfloat162float(hi));
            }
            int r = arow0 + 32*i;
            *(uint2*)&Ah[r][acol] = ph.u;
            *(uint2*)&Al[r][acol] = pl.u;
        }
#pragma unroll
        for (int i = 0; i < 2; i++) {
            float v[4] = {bR[i].x, bR[i].y, bR[i].z, bR[i].w};
            union { __nv_bfloat16 b[4]; uint2 u; } ph, pl;
#pragma unroll
            for (int j = 0; j < 4; j++) {
                __nv_bfloat16 hi = __float2bfloat16(v[j]);
                ph.b[j] = hi;
                pl.b[j] = __float2bfloat16(v[j] - __bfloat162float(hi));
            }
            int r = arow0 + 32*i;
            *(uint2*)&Bh[r][acol] = ph.u;
            *(uint2*)&Bl[r][acol] = pl.u;
        }
        __syncthreads();

        // prefetch next k-tile into registers (overlaps with mma below)
        if (kt + 1 < nk) {
            int k0 = (kt + 1) * BK;
#pragma unroll
            for (int i = 0; i < 4; i++)
                aR[i] = *(const float4*)&A[(size_t)(bm + arow0 + 32*i) * K + k0 + acol];
#pragma unroll
            for (int i = 0; i < 2; i++) {
                int gn = bn + arow0 + 32*i;
                bR[i] = (gn < N) ? *(const float4*)&B[(size_t)gn * K + k0 + acol] : zero4;
            }
        }

        // compute: two k=16 slices
#pragma unroll
        for (int kk = 0; kk < BK; kk += 16) {
            uint32_t ah[2][4], al[2][4], bhf[2][4], blf[2][4];
#pragma unroll
            for (int mi = 0; mi < 2; mi++) {
                int r   = wm + mi*16 + (lane & 15);
                int cc  = kk + ((lane >> 4) << 3);
                uint32_t off = (uint32_t)(r * LDSA + cc) * 2u;
                ldsm4(aBaseH + off, ah[mi][0], ah[mi][1], ah[mi][2], ah[mi][3]);
                ldsm4(aBaseL + off, al[mi][0], al[mi][1], al[mi][2], al[mi][3]);
            }
#pragma unroll
            for (int ng = 0; ng < 2; ng++) {
                int rn  = wn + ng*16 + (lane & 7) + (((lane >> 4) & 1) << 3);
                int cc  = kk + (((lane >> 3) & 1) << 3);
                uint32_t off = (uint32_t)(rn * LDSB + cc) * 2u;
                ldsm4(bBaseH + off, bhf[ng][0], bhf[ng][1], bhf[ng][2], bhf[ng][3]);
                ldsm4(bBaseL + off, blf[ng][0], blf[ng][1], blf[ng][2], blf[ng][3]);
            }
#pragma unroll
            for (int mi = 0; mi < 2; mi++)
#pragma unroll
                for (int ni = 0; ni < 4; ni++) {
                    int ng = ni >> 1, sub = ni & 1;
                    mma_bf16(acc[mi][ni], ah[mi], bhf[ng][sub*2], bhf[ng][sub*2+1]); // hi*hi
                    mma_bf16(acc[mi][ni], ah[mi], blf[ng][sub*2], blf[ng][sub*2+1]); // hi*lo
                    mma_bf16(acc[mi][ni], al[mi], bhf[ng][sub*2], bhf[ng][sub*2+1]); // lo*hi
                }
        }
        __syncthreads();
    }

    // epilogue
#pragma unroll
    for (int mi = 0; mi < 2; mi++)
#pragma unroll
        for (int ni = 0; ni < 4; ni++) {
            int r0 = bm + wm + mi*16 + (lane >> 2);
            int cc = bn + wn + ni*8 + ((lane & 3) << 1);
            if (cc < N) {
                *(float2*)&C[(size_t)r0 * N + cc] =
                    make_float2(acc[mi][ni][0], acc[mi][ni][1]);
                *(float2*)&C[(size_t)(r0 + 8) * N + cc] =
                    make_float2(acc[mi][ni][2], acc[mi][ni][3]);
            }
        }
}

// ---------------- scan helpers ----------------
__device__ __forceinline__ float softplus_(float v) {
    return v > 20.f ? v : log1pf(__expf(v));
}

// pass 1: per-chunk local scan with h0=0 -> E (end state), S (sum of delta)
__global__ __launch_bounds__(256)
void scan_pass1(const float* __restrict__ x, const float* __restrict__ A_log) {
    const int h = blockIdx.x * 256 + threadIdx.x;
    const int b = blockIdx.y, c = blockIdx.z;
    const int m0 = b * SEQ + c * LC;

    __shared__ float bt_s[LC][NST];
    for (int i = threadIdx.x; i < LC * NST; i += 256) {
        int t = i >> 4, j = i & 15;
        bt_s[t][j] = g_xp[(size_t)(m0 + t) * XPC + j];
    }
    float A2[NST];
#pragma unroll
    for (int n = 0; n < NST; n++) A2[n] = -__expf(A_log[n]) * 1.44269504f;
    __syncthreads();

    float E[NST];
#pragma unroll
    for (int n = 0; n < NST; n++) E[n] = 0.f;
    float S = 0.f;

    for (int t = 0; t < LC; t++) {
        float dtr = g_xp[(size_t)(m0 + t) * XPC + 2*NST + h];
        float dt  = softplus_(dtr);
        float xv  = x[(size_t)(m0 + t) * HID + h];
        S += dt;
        float dtx = dt * xv;
#pragma unroll
        for (int n = 0; n < NST; n++) {
            float dA = ex2_(A2[n] * dt);
            E[n] = fmaf(dA, E[n], bt_s[t][n] * dtx);
        }
    }
    const int cb = c * BATCHN + b;
#pragma unroll
    for (int n = 0; n < NST; n++)
        g_E[((size_t)cb * NST + n) * HID + h] = E[n];
    g_S[(size_t)cb * HID + h] = S;
}

// combine: sequential over NCHUNK chunks -> per-chunk initial states
__global__ __launch_bounds__(256)
void scan_combine(const float* __restrict__ A_log) {
    const int idx = blockIdx.x * 256 + threadIdx.x;  // 0..B*H-1
    const int b = idx >> 10;
    const int h = idx & (HID - 1);
    float A2[NST];
#pragma unroll
    for (int n = 0; n < NST; n++) A2[n] = -__expf(A_log[n]) * 1.44269504f;

    float hr[NST];
#pragma unroll
    for (int n = 0; n < NST; n++) hr[n] = 0.f;

    for (int c = 0; c < NCHUNK; c++) {
        const int cb = c * BATCHN + b;
#pragma unroll
        for (int n = 0; n < NST; n++)
            g_h0[((size_t)cb * NST + n) * HID + h] = hr[n];
        float S = g_S[(size_t)cb * HID + h];
#pragma unroll
        for (int n = 0; n < NST; n++) {
            float D = ex2_(A2[n] * S);
            hr[n] = fmaf(D, hr[n], g_E[((size_t)cb * NST + n) * HID + h]);
        }
    }
}

// pass 2: per-chunk scan with correct h0 -> y
__global__ __launch_bounds__(256)
void scan_pass2(const float* __restrict__ x, const float* __restrict__ A_log,
                const float* __restrict__ Dw) {
    const int h = blockIdx.x * 256 + threadIdx.x;
    const int b = blockIdx.y, c = blockIdx.z;
    const int m0 = b * SEQ + c * LC;

    __shared__ float bc_s[LC][2 * NST];
    for (int i = threadIdx.x; i < LC * 2 * NST; i += 256) {
        int t = i >> 5, j = i & 31;
        bc_s[t][j] = g_xp[(size_t)(m0 + t) * XPC + j];
    }
    float A2[NST];
#pragma unroll
    for (int n = 0; n < NST; n++) A2[n] = -__expf(A_log[n]) * 1.44269504f;
    __syncthreads();

    const int cb = c * BATCHN + b;
    float hreg[NST];
#pragma unroll
    for (int n = 0; n < NST; n++)
        hreg[n] = g_h0[((size_t)cb * NST + n) * HID + h];
    const float Dh = Dw[h];

    for (int t = 0; t < LC; t++) {
        float dtr = g_xp[(size_t)(m0 + t) * XPC + 2*NST + h];
        float dt  = softplus_(dtr);
        float xv  = x[(size_t)(m0 + t) * HID + h];
        float dtx = dt * xv;
        float y   = Dh * xv;
#pragma unroll
        for (int n = 0; n < NST; n++) {
            float dA = ex2_(A2[n] * dt);
            hreg[n] = fmaf(dA, hreg[n], bc_s[t][n] * dtx);
            y = fmaf(bc_s[t][NST + n], hreg[n], y);
        }
        g_y[(size_t)(m0 + t) * HID + h] = y;
    }
}

// ---------------- launch ----------------
extern "C" void kernel_launch(void* const* d_in, const int* in_sizes, int n_in,
                              void* d_out, int out_size) {
    // positional default (x, Wx, A_log, D, Wout), refined by unique sizes
    const float* x    = (const float*)d_in[0];
    const float* Wx   = (const float*)d_in[1];
    const float* Alog = (const float*)d_in[2];
    const float* Dw   = (const float*)d_in[3];
    const float* Wout = (const float*)d_in[4];
    for (int i = 0; i < n_in; i++) {
        const float* p = (const float*)d_in[i];
        switch (in_sizes[i]) {
            case M_ROWS * HID: x    = p; break;  // 8388608
            case XPC * HID:    Wx   = p; break;  // 1081344
            case NST:          Alog = p; break;  // 16
            case HID:          Dw   = p; break;  // 1024
            case HID * HID:    Wout = p; break;  // 1048576
        }
    }

    float *xp_d = nullptr, *y_d = nullptr;
    cudaGetSymbolAddress((void**)&xp_d, g_xp);
    cudaGetSymbolAddress((void**)&y_d, g_y);

    dim3 blk(256);
    // GEMM1: g_xp = x @ Wx^T   (M=8192, N=1056, K=1024)
    gemm_nt<<<dim3((XPC + BN - 1) / BN, M_ROWS / BM), blk>>>(x, Wx, xp_d,
                                                            M_ROWS, XPC, HID);
    // chunked selective scan
    scan_pass1 <<<dim3(HID / 256, BATCHN, NCHUNK), blk>>>(x, Alog);
    scan_combine<<<BATCHN * HID / 256, blk>>>(Alog);
    scan_pass2 <<<dim3(HID / 256, BATCHN, NCHUNK), blk>>>(x, Alog, Dw);
    // GEMM2: out = y @ Wout^T  (M=8192, N=1024, K=1024)
    gemm_nt<<<dim3(HID / BN, M_ROWS / BM), blk>>>(y_d, Wout, (float*)d_out,
                                                  M_ROWS, HID, HID);
}

// round 5
// speedup vs baseline: 1.1369x; 1.1369x over previous
#include <cuda_runtime.h>
#include <cuda_bf16.h>
#include <cstdint>

#define HID   1024
#define NST   16
#define BATCHN 4
#define SEQ   2048
#define XPC   (2*NST + HID)          // 1056
#define M_ROWS (BATCHN*SEQ)          // 8192
#define NCHUNK 64
#define LC    (SEQ/NCHUNK)           // 32

// ---------------- scratch (no allocations allowed) ----------------
__device__ float g_xp[M_ROWS * XPC];                 // x @ Wx^T
__device__ float g_y [M_ROWS * HID];                 // scan output
__device__ float g_dt[M_ROWS * HID];                 // cached softplus(delta)
__device__ float g_E [NCHUNK*BATCHN*NST*HID];        // per-chunk local end state
__device__ float g_S [NCHUNK*BATCHN*HID];            // per-chunk sum of delta
__device__ float g_h0[NCHUNK*BATCHN*NST*HID];        // per-chunk initial state

// ---------------- helpers ----------------
__device__ __forceinline__ float ex2_(float x) {
    float y;
    asm("ex2.approx.ftz.f32 %0, %1;" : "=f"(y) : "f"(x));
    return y;
}

__device__ __forceinline__ void ldsm4(uint32_t addr, uint32_t& r0, uint32_t& r1,
                                      uint32_t& r2, uint32_t& r3) {
    asm volatile("ldmatrix.sync.aligned.m8n8.x4.shared.b16 {%0,%1,%2,%3}, [%4];"
                 : "=r"(r0), "=r"(r1), "=r"(r2), "=r"(r3) : "r"(addr));
}

__device__ __forceinline__ void mma_bf16(float* c, const uint32_t* a,
                                         uint32_t b0, uint32_t b1) {
    asm volatile(
        "mma.sync.aligned.m16n8k16.row.col.f32.bf16.bf16.f32 "
        "{%0,%1,%2,%3}, {%4,%5,%6,%7}, {%8,%9}, {%0,%1,%2,%3};"
        : "+f"(c[0]), "+f"(c[1]), "+f"(c[2]), "+f"(c[3])
        : "r"(a[0]), "r"(a[1]), "r"(a[2]), "r"(a[3]), "r"(b0), "r"(b1));
}

// ---------------- GEMM: C[M,N] = A[M,K] * B[N,K]^T, fp32 via split-bf16 ----------------
#define BM 128
#define BN 64
#define BK 32
#define LDSA 40   // padded stride (bf16 elems) -> conflict-free ldmatrix
#define LDSB 40

__global__ __launch_bounds__(256)
void gemm_nt(const float* __restrict__ A, const float* __restrict__ B,
             float* __restrict__ C, int M, int N, int K) {
    __shared__ __nv_bfloat16 Ah[BM][LDSA], Al[BM][LDSA];
    __shared__ __nv_bfloat16 Bh[BN][LDSB], Bl[BN][LDSB];

    const int tid  = threadIdx.x;
    const int lane = tid & 31;
    const int warp = tid >> 5;
    const int wm   = (warp >> 1) * 32;   // 0,32,64,96
    const int wn   = (warp & 1) * 32;    // 0,32
    const int bm   = blockIdx.y * BM;
    const int bn   = blockIdx.x * BN;

    const int acol  = (tid & 7) << 2;    // 0..28
    const int arow0 = tid >> 3;          // 0..31

    float acc[2][4][4];
#pragma unroll
    for (int i = 0; i < 2; i++)
#pragma unroll
        for (int j = 0; j < 4; j++)
#pragma unroll
            for (int k = 0; k < 4; k++) acc[i][j][k] = 0.f;

    const uint32_t aBaseH = (uint32_t)__cvta_generic_to_shared(&Ah[0][0]);
    const uint32_t aBaseL = (uint32_t)__cvta_generic_to_shared(&Al[0][0]);
    const uint32_t bBaseH = (uint32_t)__cvta_generic_to_shared(&Bh[0][0]);
    const uint32_t bBaseL = (uint32_t)__cvta_generic_to_shared(&Bl[0][0]);

    float4 aR[4], bR[2];
    const float4 zero4 = make_float4(0.f, 0.f, 0.f, 0.f);

    // prologue load (k-tile 0)
#pragma unroll
    for (int i = 0; i < 4; i++)
        aR[i] = *(const float4*)&A[(size_t)(bm + arow0 + 32*i) * K + acol];
#pragma unroll
    for (int i = 0; i < 2; i++) {
        int gn = bn + arow0 + 32*i;
        bR[i] = (gn < N) ? *(const float4*)&B[(size_t)gn * K + acol] : zero4;
    }

    const int nk = K / BK;
    for (int kt = 0; kt < nk; ++kt) {
        // split & store staged regs to smem
#pragma unroll
        for (int i = 0; i < 4; i++) {
            float v[4] = {aR[i].x, aR[i].y, aR[i].z, aR[i].w};
            union { __nv_bfloat16 b[4]; uint2 u; } ph, pl;
#pragma unroll
            for (int j = 0; j < 4; j++) {
                __nv_bfloat16 hi = __float2bfloat16(v[j]);
                ph.b[j] = hi;
                pl.b[j] = __float2bfloat16(v[j] - __bfloat162float(hi));
            }
            int r = arow0 + 32*i;
            *(uint2*)&Ah[r][acol] = ph.u;
            *(uint2*)&Al[r][acol] = pl.u;
        }
#pragma unroll
        for (int i = 0; i < 2; i++) {
            float v[4] = {bR[i].x, bR[i].y, bR[i].z, bR[i].w};
            union { __nv_bfloat16 b[4]; uint2 u; } ph, pl;
#pragma unroll
            for (int j = 0; j < 4; j++) {
                __nv_bfloat16 hi = __float2bfloat16(v[j]);
                ph.b[j] = hi;
                pl.b[j] = __float2bfloat16(v[j] - __bfloat162float(hi));
            }
            int r = arow0 + 32*i;
            *(uint2*)&Bh[r][acol] = ph.u;
            *(uint2*)&Bl[r][acol] = pl.u;
        }
        __syncthreads();

        // prefetch next k-tile into registers (overlaps with mma below)
        if (kt + 1 < nk) {
            int k0 = (kt + 1) * BK;
#pragma unroll
            for (int i = 0; i < 4; i++)
                aR[i] = *(const float4*)&A[(size_t)(bm + arow0 + 32*i) * K + k0 + acol];
#pragma unroll
            for (int i = 0; i < 2; i++) {
                int gn = bn + arow0 + 32*i;
                bR[i] = (gn < N) ? *(const float4*)&B[(size_t)gn * K + k0 + acol] : zero4;
            }
        }

        // compute: two k=16 slices
#pragma unroll
        for (int kk = 0; kk < BK; kk += 16) {
            uint32_t ah[2][4], al[2][4], bhf[2][4], blf[2][4];
#pragma unroll
            for (int mi = 0; mi < 2; mi++) {
                int r   = wm + mi*16 + (lane & 15);
                int cc  = kk + ((lane >> 4) << 3);
                uint32_t off = (uint32_t)(r * LDSA + cc) * 2u;
                ldsm4(aBaseH + off, ah[mi][0], ah[mi][1], ah[mi][2], ah[mi][3]);
                ldsm4(aBaseL + off, al[mi][0], al[mi][1], al[mi][2], al[mi][3]);
            }
#pragma unroll
            for (int ng = 0; ng < 2; ng++) {
                int rn  = wn + ng*16 + (lane & 7) + (((lane >> 4) & 1) << 3);
                int cc  = kk + (((lane >> 3) & 1) << 3);
                uint32_t off = (uint32_t)(rn * LDSB + cc) * 2u;
                ldsm4(bBaseH + off, bhf[ng][0], bhf[ng][1], bhf[ng][2], bhf[ng][3]);
                ldsm4(bBaseL + off, blf[ng][0], blf[ng][1], blf[ng][2], blf[ng][3]);
            }
#pragma unroll
            for (int mi = 0; mi < 2; mi++)
#pragma unroll
                for (int ni = 0; ni < 4; ni++) {
                    int ng = ni >> 1, sub = ni & 1;
                    mma_bf16(acc[mi][ni], ah[mi], bhf[ng][sub*2], bhf[ng][sub*2+1]); // hi*hi
                    mma_bf16(acc[mi][ni], ah[mi], blf[ng][sub*2], blf[ng][sub*2+1]); // hi*lo
                    mma_bf16(acc[mi][ni], al[mi], bhf[ng][sub*2], bhf[ng][sub*2+1]); // lo*hi
                }
        }
        __syncthreads();
    }

    // epilogue
#pragma unroll
    for (int mi = 0; mi < 2; mi++)
#pragma unroll
        for (int ni = 0; ni < 4; ni++) {
            int r0 = bm + wm + mi*16 + (lane >> 2);
            int cc = bn + wn + ni*8 + ((lane & 3) << 1);
            if (cc < N) {
                *(float2*)&C[(size_t)r0 * N + cc] =
                    make_float2(acc[mi][ni][0], acc[mi][ni][1]);
                *(float2*)&C[(size_t)(r0 + 8) * N + cc] =
                    make_float2(acc[mi][ni][2], acc[mi][ni][3]);
            }
        }
}

// ---------------- scan helpers ----------------
// branch-free fast softplus: max(v,0) + log(1 + exp(-|v|))
__device__ __forceinline__ float softplus_(float v) {
    return fmaxf(v, 0.f) + __logf(1.f + __expf(-fabsf(v)));
}

// pass 1: per-chunk local scan with h0=0 -> E (end state), S (sum of delta).
// Also caches dt = softplus(delta) for pass 2.
__global__ __launch_bounds__(256)
void scan_pass1(const float* __restrict__ x, const float* __restrict__ A_log) {
    const int h = blockIdx.x * 256 + threadIdx.x;
    const int b = blockIdx.y, c = blockIdx.z;
    const int m0 = b * SEQ + c * LC;

    __shared__ float bt_s[LC][NST];
    for (int i = threadIdx.x; i < LC * NST; i += 256) {
        int t = i >> 4, j = i & 15;
        bt_s[t][j] = g_xp[(size_t)(m0 + t) * XPC + j];
    }
    float A2[NST];
#pragma unroll
    for (int n = 0; n < NST; n++) A2[n] = -__expf(A_log[n]) * 1.44269504f;
    __syncthreads();

    float E[NST];
#pragma unroll
    for (int n = 0; n < NST; n++) E[n] = 0.f;
    float S = 0.f;

#pragma unroll 2
    for (int t = 0; t < LC; t++) {
        float dtr = g_xp[(size_t)(m0 + t) * XPC + 2*NST + h];
        float dt  = softplus_(dtr);
        float xv  = x[(size_t)(m0 + t) * HID + h];
        g_dt[(size_t)(m0 + t) * HID + h] = dt;
        S += dt;
        float dtx = dt * xv;
#pragma unroll
        for (int n = 0; n < NST; n++) {
            float dA = ex2_(A2[n] * dt);
            E[n] = fmaf(dA, E[n], bt_s[t][n] * dtx);
        }
    }
    const int cb = c * BATCHN + b;
#pragma unroll
    for (int n = 0; n < NST; n++)
        g_E[((size_t)cb * NST + n) * HID + h] = E[n];
    g_S[(size_t)cb * HID + h] = S;
}

// combine: sequential over NCHUNK chunks, parallel over (b, n, h).
// Software-pipelined loads so the serial chain is ex2->fma only.
__global__ __launch_bounds__(256)
void scan_combine(const float* __restrict__ A_log) {
    const int idx = blockIdx.x * 256 + threadIdx.x;  // 0..B*N*H-1
    const int h = idx & (HID - 1);
    const int n = (idx >> 10) & (NST - 1);
    const int b = idx >> 14;
    const float A2 = -__expf(A_log[n]) * 1.44269504f;

    float hr = 0.f;
    // prefetch chunk 0
    float Ecur = g_E[((size_t)(0 * BATCHN + b) * NST + n) * HID + h];
    float Scur = g_S[(size_t)(0 * BATCHN + b) * HID + h];

    for (int c = 0; c < NCHUNK; c++) {
        float Enext = 0.f, Snext = 0.f;
        if (c + 1 < NCHUNK) {
            const int cb1 = (c + 1) * BATCHN + b;
            Enext = g_E[((size_t)cb1 * NST + n) * HID + h];
            Snext = g_S[(size_t)cb1 * HID + h];
        }
        const int cb = c * BATCHN + b;
        g_h0[((size_t)cb * NST + n) * HID + h] = hr;
        hr = fmaf(ex2_(A2 * Scur), hr, Ecur);
        Ecur = Enext; Scur = Snext;
    }
}

// pass 2: per-chunk scan with correct h0 -> y (dt loaded from cache)
__global__ __launch_bounds__(256)
void scan_pass2(const float* __restrict__ x, const float* __restrict__ A_log,
                const float* __restrict__ Dw) {
    const int h = blockIdx.x * 256 + threadIdx.x;
    const int b = blockIdx.y, c = blockIdx.z;
    const int m0 = b * SEQ + c * LC;

    __shared__ float bc_s[LC][2 * NST];
    for (int i = threadIdx.x; i < LC * 2 * NST; i += 256) {
        int t = i >> 5, j = i & 31;
        bc_s[t][j] = g_xp[(size_t)(m0 + t) * XPC + j];
    }
    float A2[NST];
#pragma unroll
    for (int n = 0; n < NST; n++) A2[n] = -__expf(A_log[n]) * 1.44269504f;
    __syncthreads();

    const int cb = c * BATCHN + b;
    float hreg[NST];
#pragma unroll
    for (int n = 0; n < NST; n++)
        hreg[n] = g_h0[((size_t)cb * NST + n) * HID + h];
    const float Dh = Dw[h];

#pragma unroll 2
    for (int t = 0; t < LC; t++) {
        float dt  = g_dt[(size_t)(m0 + t) * HID + h];
        float xv  = x[(size_t)(m0 + t) * HID + h];
        float dtx = dt * xv;
        float y   = Dh * xv;
#pragma unroll
        for (int n = 0; n < NST; n++) {
            float dA = ex2_(A2[n] * dt);
            hreg[n] = fmaf(dA, hreg[n], bc_s[t][n] * dtx);
            y = fmaf(bc_s[t][NST + n], hreg[n], y);
        }
        g_y[(size_t)(m0 + t) * HID + h] = y;
    }
}

// ---------------- launch ----------------
extern "C" void kernel_launch(void* const* d_in, const int* in_sizes, int n_in,
                              void* d_out, int out_size) {
    // positional default (x, Wx, A_log, D, Wout), refined by unique sizes
    const float* x    = (const float*)d_in[0];
    const float* Wx   = (const float*)d_in[1];
    const float* Alog = (const float*)d_in[2];
    const float* Dw   = (const float*)d_in[3];
    const float* Wout = (const float*)d_in[4];
    for (int i = 0; i < n_in; i++) {
        const float* p = (const float*)d_in[i];
        switch (in_sizes[i]) {
            case M_ROWS * HID: x    = p; break;  // 8388608
            case XPC * HID:    Wx   = p; break;  // 1081344
            case NST:          Alog = p; break;  // 16
            case HID:          Dw   = p; break;  // 1024
            case HID * HID:    Wout = p; break;  // 1048576
        }
    }

    float *xp_d = nullptr, *y_d = nullptr;
    cudaGetSymbolAddress((void**)&xp_d, g_xp);
    cudaGetSymbolAddress((void**)&y_d, g_y);

    dim3 blk(256);
    // GEMM1: g_xp = x @ Wx^T   (M=8192, N=1056, K=1024)
    gemm_nt<<<dim3((XPC + BN - 1) / BN, M_ROWS / BM), blk>>>(x, Wx, xp_d,
                                                            M_ROWS, XPC, HID);
    // chunked selective scan
    scan_pass1 <<<dim3(HID / 256, BATCHN, NCHUNK), blk>>>(x, Alog);
    scan_combine<<<BATCHN * NST * HID / 256, blk>>>(Alog);
    scan_pass2 <<<dim3(HID / 256, BATCHN, NCHUNK), blk>>>(x, Alog, Dw);
    // GEMM2: out = y @ Wout^T  (M=8192, N=1024, K=1024)
    gemm_nt<<<dim3(HID / BN, M_ROWS / BM), blk>>>(y_d, Wout, (float*)d_out,
                                                  M_ROWS, HID, HID);
}